// round 3
// baseline (speedup 1.0000x reference)
#include <cuda_runtime.h>
#include <cstdint>

// Problem constants
#define B_TOTAL  128
#define C_IN     32
#define C_OUT    8
#define S_TOTAL  8192

// Tiling
#define S_TILE   64      // s-values per block (16 float4 groups)
#define B_CHUNK  32      // batches per block
#define THREADS  256

// Scratch for ws[j,s] = sum_i w1[i,j,s]  (1 MB)
__device__ float g_ws[C_IN * S_TOTAL];

// ---------------------------------------------------------------------------
// helpers
// ---------------------------------------------------------------------------
__device__ __forceinline__ float tanh_fast(float x) {
    float y;
    asm("tanh.approx.f32 %0, %1;" : "=f"(y) : "f"(x));
    return y;
}

// Accurate tanh for final output (rel err ~1e-6)
__device__ __forceinline__ float tanh_acc(float x) {
    float xc = fminf(fmaxf(x, -20.0f), 20.0f);
    float e  = __expf(2.0f * xc);
    return __fdividef(e - 1.0f, e + 1.0f);
}

__device__ __forceinline__ float4 ld4(const float* p) {
    return *reinterpret_cast<const float4*>(p);
}
__device__ __forceinline__ void st4(float* p, float4 v) {
    *reinterpret_cast<float4*>(p) = v;
}

__device__ __forceinline__ float4 tanh4_of_prod(float4 a, float4 b) {
    float4 r;
    r.x = tanh_fast(a.x * b.x);
    r.y = tanh_fast(a.y * b.y);
    r.z = tanh_fast(a.z * b.z);
    r.w = tanh_fast(a.w * b.w);
    return r;
}

__device__ __forceinline__ void fma4(float4& acc, float4 h, float4 w) {
    acc.x = fmaf(h.x, w.x, acc.x);
    acc.y = fmaf(h.y, w.y, acc.y);
    acc.z = fmaf(h.z, w.z, acc.z);
    acc.w = fmaf(h.w, w.w, acc.w);
}

__device__ __forceinline__ float4 add4(float4 a, float4 b) {
    return make_float4(a.x + b.x, a.y + b.y, a.z + b.z, a.w + b.w);
}

__device__ __forceinline__ float4 shfl_xor4(float4 v, int m) {
    float4 r;
    r.x = __shfl_xor_sync(0xffffffffu, v.x, m);
    r.y = __shfl_xor_sync(0xffffffffu, v.y, m);
    r.z = __shfl_xor_sync(0xffffffffu, v.z, m);
    r.w = __shfl_xor_sync(0xffffffffu, v.w, m);
    return r;
}

// XOR swizzle: makes h smem conflict-free for BOTH the store pattern
// (warp lanes vary in j low bits) and the load pattern (lanes vary in j>>3).
__device__ __forceinline__ int swz(int j, int col) {
    return col ^ ((((j & 3) ^ (j >> 3)) & 3) << 1);
}

// ---------------------------------------------------------------------------
// Kernel 1: ws[j,s] = sum_i w1[i,j,s]      w1: [C_IN(i)][C_IN(j)][S]
// ---------------------------------------------------------------------------
__global__ __launch_bounds__(256) void ws_kernel(const float* __restrict__ w1) {
    int t = blockIdx.x * blockDim.x + threadIdx.x;   // 0 .. C_IN*S/4 - 1
    int j   = t >> 11;             // 2048 float4 groups per j row
    int grp = t & 2047;
    const float* p = w1 + (size_t)j * S_TOTAL + grp * 4;
    float4 acc = make_float4(0.f, 0.f, 0.f, 0.f);
#pragma unroll
    for (int i = 0; i < C_IN; i++) {
        float4 v = ld4(p + (size_t)i * C_IN * S_TOTAL);
        acc.x += v.x; acc.y += v.y; acc.z += v.z; acc.w += v.w;
    }
    st4(&g_ws[(size_t)j * S_TOTAL + grp * 4], acc);
}

// ---------------------------------------------------------------------------
// Kernel 2: fused stage1 + stage2.
//
// Thread decode (phase B): t = (sg<<4)|(op<<2)|jq
//   sg  : s4-group 0..15           (which float4 of the s-tile)
//   op  : output-channel pair 0..3 (owns o = 2op, 2op+1)
//   jq  : j-quarter 0..3           (owns j = 8jq .. 8jq+7)
// w2 in registers: 2 o x 8 j = 16 float4 = 64 regs.
// Each h LDS.128 feeds 8 FFMAs. jq partials combined via warp butterfly
// (lane bits 0-1 == jq). Double-buffered h -> one barrier per batch.
// ---------------------------------------------------------------------------
__global__ void __launch_bounds__(THREADS, 2) fused_kernel(
    const float* __restrict__ x,     // [B][C_IN][S]
    const float* __restrict__ w2,    // [C_OUT][C_IN][S]
    const float* __restrict__ bias,  // [C_OUT][S]
    float* __restrict__ out)         // [B][C_OUT][S]
{
    __shared__ float4 hb[2][C_IN][S_TILE / 4];   // 2 x 8 KB

    const int t     = threadIdx.x;
    const int sBase = blockIdx.x * S_TILE;
    const int bBase = blockIdx.y * B_CHUNK;

    // phase-B ids
    const int sg = t >> 4;           // 0..15
    const int op = (t >> 2) & 3;     // 0..3
    const int jq = t & 3;            // 0..3
    const int ob = 2 * op + (jq & 1);// this lane's output channel after reduction

    // phase-A ids (h production): thread -> (jA, groups sgA and sgA+8)
    const int jA  = t >> 3;          // 0..31
    const int sgA = t & 7;           // 0..7

    // ws regs (block-invariant)
    const float4 ws0 = ld4(&g_ws[jA * S_TOTAL + sBase + sgA * 4]);
    const float4 ws1 = ld4(&g_ws[jA * S_TOTAL + sBase + (sgA + 8) * 4]);

    // w2 regs: 2 o x 8 j float4
    float4 w2a[8], w2b[8];
    {
        const float* p0 = w2 + ((size_t)(2 * op) * C_IN + jq * 8) * S_TOTAL
                             + sBase + sg * 4;
        const float* p1 = p0 + (size_t)C_IN * S_TOTAL;
#pragma unroll
        for (int jj = 0; jj < 8; jj++) {
            w2a[jj] = ld4(p0 + (size_t)jj * S_TOTAL);
            w2b[jj] = ld4(p1 + (size_t)jj * S_TOTAL);
        }
    }
    const float4 biasr = ld4(&bias[(size_t)ob * S_TOTAL + sBase + sg * 4]);

    // x stream for this thread's (jA, sgA) lanes
    const float* xrow = x + ((size_t)bBase * C_IN + jA) * S_TOTAL + sBase + sgA * 4;
    const size_t xstep = (size_t)C_IN * S_TOTAL;   // batch stride

    // produce h(0) into buffer 0
    float4 x0 = ld4(xrow);
    float4 x1 = ld4(xrow + 32);
    hb[0][jA][swz(jA, sgA)]     = tanh4_of_prod(x0, ws0);
    hb[0][jA][swz(jA, sgA + 8)] = tanh4_of_prod(x1, ws1);
    // prefetch x(1)
    xrow += xstep;
    x0 = ld4(xrow);
    x1 = ld4(xrow + 32);

    for (int b = 0; b < B_CHUNK; b++) {
        __syncthreads();                 // h(b) ready in hb[b&1]
        const int p = b & 1;

        // produce h(b+1) into the other buffer; prefetch x(b+2)
        if (b + 1 < B_CHUNK) {
            hb[p ^ 1][jA][swz(jA, sgA)]     = tanh4_of_prod(x0, ws0);
            hb[p ^ 1][jA][swz(jA, sgA + 8)] = tanh4_of_prod(x1, ws1);
            if (b + 2 < B_CHUNK) {
                xrow += xstep;
                x0 = ld4(xrow);
                x1 = ld4(xrow + 32);
            }
        }

        // phase B: partial contraction over this thread's 8 j values
        float4 a0 = make_float4(0.f, 0.f, 0.f, 0.f);
        float4 a1 = make_float4(0.f, 0.f, 0.f, 0.f);
#pragma unroll
        for (int jj = 0; jj < 8; jj++) {
            const int j = jq * 8 + jj;
            float4 hv = hb[p][j][swz(j, sg)];
            fma4(a0, hv, w2a[jj]);
            fma4(a1, hv, w2b[jj]);
        }

        // butterfly over jq (lane bits 0-1):
        // stage 1 (xor 1): even lanes keep a0 (o=2op), odd keep a1 (o=2op+1)
        float4 send = (jq & 1) ? a0 : a1;
        float4 recv = shfl_xor4(send, 1);
        float4 r = (jq & 1) ? add4(a1, recv) : add4(a0, recv);
        // stage 2 (xor 2): same o, sum the other jq pair
        r = add4(r, shfl_xor4(r, 2));

        // lanes jq<2 hold the full sum for o = 2op + jq
        if (jq < 2) {
            float4 v = add4(r, biasr);
            float4 ov;
            ov.x = tanh_acc(v.x);
            ov.y = tanh_acc(v.y);
            ov.z = tanh_acc(v.z);
            ov.w = tanh_acc(v.w);
            st4(&out[((size_t)(bBase + b) * C_OUT + ob) * S_TOTAL + sBase + sg * 4], ov);
        }
    }
}

// ---------------------------------------------------------------------------
// launch
// ---------------------------------------------------------------------------
extern "C" void kernel_launch(void* const* d_in, const int* in_sizes, int n_in,
                              void* d_out, int out_size) {
    const float* x    = (const float*)d_in[0];
    const float* w1   = (const float*)d_in[1];
    const float* w2   = (const float*)d_in[2];
    const float* bias = (const float*)d_in[3];
    float* out = (float*)d_out;

    ws_kernel<<<(C_IN * S_TOTAL / 4) / 256, 256>>>(w1);

    dim3 grid(S_TOTAL / S_TILE, B_TOTAL / B_CHUNK);   // (128, 4) = 512 blocks
    fused_kernel<<<grid, THREADS>>>(x, w2, bias, out);
}